// round 4
// baseline (speedup 1.0000x reference)
#include <cuda_runtime.h>

// Dense CRF pairwise loss, B=1, C=2, H=W=96.
// K_ij = 2^(g_i.g_j - h_i - h_j), g = 5-dim scaled feature, h = |g|^2/2.
// Tile-symmetry: sum over a<=b tile pairs, off-diag doubled.
// Per-i weight hoisted: Sum_j k*(A_i+B_i*p_j) = A_i*Sum k + B_i*Sum k*p_j.

#define Hdim   96
#define Wdim   96
#define NPIX   9216
#define TPB    1024
#define ITILE  1024
#define NTILES 9             // 9216/1024
#define NTPAIR 45            // triangle incl diagonal
#define NCHUNK 3
#define NBLK   (NTPAIR*NCHUNK)  // 135 blocks = 1 wave
#define JP_TILE (ITILE/2)    // 512 j-pairs per tile
#define JPMAX  171           // ceil(512/3)

__device__ float g_part[NBLK];
__device__ int   g_cnt = 0;

typedef unsigned long long u64;

__device__ __forceinline__ u64 splat2(float v) {
    u64 r; asm("mov.b64 %0,{%1,%1};" : "=l"(r) : "f"(v)); return r;
}
__device__ __forceinline__ u64 pk2(float a, float b) {
    u64 r; asm("mov.b64 %0,{%1,%2};" : "=l"(r) : "f"(a), "f"(b)); return r;
}
__device__ __forceinline__ void up2(u64 v, float& a, float& b) {
    asm("mov.b64 {%0,%1},%2;" : "=f"(a), "=f"(b) : "l"(v));
}
__device__ __forceinline__ u64 fma2(u64 a, u64 b, u64 c) {
    u64 d; asm("fma.rn.f32x2 %0,%1,%2,%3;" : "=l"(d) : "l"(a), "l"(b), "l"(c)); return d;
}
__device__ __forceinline__ u64 add2(u64 a, u64 b) {
    u64 d; asm("add.rn.f32x2 %0,%1,%2;" : "=l"(d) : "l"(a), "l"(b)); return d;
}
__device__ __forceinline__ float ex2f(float x) {
    float r; asm("ex2.approx.ftz.f32 %0,%1;" : "=f"(r) : "f"(x)); return r;
}

__device__ __forceinline__ void pix_feat(const float* __restrict__ probs,
                                         const float* __restrict__ image, int n,
                                         float& gy, float& gx, float& gr, float& gg,
                                         float& gb, float& nh, float& p) {
    const float SXY  = 0.080074306f;   // sqrt(log2e/225)
    const float SRGB = 9.6083684f;     // sqrt(64*log2e)
    gy = (float)(n / Wdim) * SXY;
    gx = (float)(n % Wdim) * SXY;
    gr = image[n] * SRGB;
    gg = image[NPIX + n] * SRGB;
    gb = image[2 * NPIX + n] * SRGB;
    nh = -0.5f * (gy*gy + gx*gx + gr*gr + gg*gg + gb*gb);
    p  = probs[n];
}

__global__ void __launch_bounds__(TPB) crf_fused(const float* __restrict__ probs,
                                                 const float* __restrict__ image,
                                                 float* __restrict__ out) {
    // j-features packed as f32x2 pairs: LDS.128 reg pairs feed fma.f32x2 directly
    __shared__ ulonglong2 sA[JPMAX];   // {gy01, gx01}
    __shared__ ulonglong2 sB[JPMAX];   // {gr01, gg01}
    __shared__ ulonglong2 sC[JPMAX];   // {gb01, nh01}
    __shared__ u64        sP[JPMAX];   // p01
    __shared__ float      ws[TPB / 32];
    __shared__ bool       isLast;

    const int tid = threadIdx.x;
    const int bid = blockIdx.x;
    const int pairIdx = bid / NCHUNK;
    const int chunk   = bid % NCHUNK;

    int a = 0, b = 0, idx = pairIdx;
    #pragma unroll
    for (int aa = 0; aa < NTILES; ++aa) {
        int cnt = NTILES - aa;
        if (idx < cnt) { a = aa; b = aa + idx; break; }
        idx -= cnt;
    }

    const int jp0 = b * JP_TILE + (chunk * JP_TILE) / NCHUNK;
    const int jp1 = b * JP_TILE + ((chunk + 1) * JP_TILE) / NCHUNK;
    const int nJp = jp1 - jp0;

    if (tid < nJp) {
        int j0 = 2 * (jp0 + tid);
        float gy0, gx0, gr0, gg0, gb0, nh0, p0;
        float gy1, gx1, gr1, gg1, gb1, nh1, p1;
        pix_feat(probs, image, j0,     gy0, gx0, gr0, gg0, gb0, nh0, p0);
        pix_feat(probs, image, j0 + 1, gy1, gx1, gr1, gg1, gb1, nh1, p1);
        sA[tid] = make_ulonglong2(pk2(gy0, gy1), pk2(gx0, gx1));
        sB[tid] = make_ulonglong2(pk2(gr0, gr1), pk2(gg0, gg1));
        sC[tid] = make_ulonglong2(pk2(gb0, gb1), pk2(nh0, nh1));
        sP[tid] = pk2(p0, p1);
    }

    // one i-row per thread
    const float wscale = (a == b) ? 1.0f : 2.0f;
    const int i = a * ITILE + tid;
    float gy, gx, gr, gg, gb, nh, p;
    pix_feat(probs, image, i, gy, gx, gr, gg, gb, nh, p);
    const u64 gyi = splat2(gy), gxi = splat2(gx);
    const u64 gri = splat2(gr), ggi = splat2(gg), gbi = splat2(gb);
    const u64 nhi = splat2(nh);
    const float Aiw = wscale * p;
    const float Biw = wscale * (1.0f - 2.0f * p);
    u64 accA = 0ull, accB = 0ull;   // Sum k ; Sum k*pj
    __syncthreads();

    #pragma unroll 2
    for (int jp = 0; jp < nJp; ++jp) {
        ulonglong2 A = sA[jp], B = sB[jp], C = sC[jp];
        u64 pj = sP[jp];
        u64 t = add2(nhi, C.y);
        t = fma2(gyi, A.x, t);
        t = fma2(gxi, A.y, t);
        t = fma2(gri, B.x, t);
        t = fma2(ggi, B.y, t);
        t = fma2(gbi, C.x, t);
        float t0, t1; up2(t, t0, t1);
        u64 k = pk2(ex2f(t0), ex2f(t1));
        accA = add2(accA, k);
        accB = fma2(k, pj, accB);
    }

    // apply per-i weights, block reduce (fixed order -> deterministic)
    float a0, a1, b0, b1;
    up2(accA, a0, a1);
    up2(accB, b0, b1);
    float s = Aiw * (a0 + a1) + Biw * (b0 + b1);
    #pragma unroll
    for (int off = 16; off > 0; off >>= 1)
        s += __shfl_down_sync(0xffffffffu, s, off);
    if ((tid & 31) == 0) ws[tid >> 5] = s;
    __syncthreads();
    if (tid == 0) {
        float t = 0.0f;
        #pragma unroll
        for (int k = 0; k < TPB / 32; ++k) t += ws[k];
        g_part[bid] = t;
        __threadfence();
        int old = atomicAdd(&g_cnt, 1);
        isLast = (old == NBLK - 1);
    }
    __syncthreads();
    if (isLast && tid < 32) {
        __threadfence();
        float acc2 = 0.0f;
        #pragma unroll
        for (int k = tid; k < NBLK; k += 32) acc2 += __ldcg(&g_part[k]);
        #pragma unroll
        for (int off = 16; off > 0; off >>= 1)
            acc2 += __shfl_down_sync(0xffffffffu, acc2, off);
        if (tid == 0) {
            out[0] = acc2 * (1.0f / (float)NPIX);
            g_cnt = 0;   // reset for next graph replay
        }
    }
}

extern "C" void kernel_launch(void* const* d_in, const int* in_sizes, int n_in,
                              void* d_out, int out_size) {
    const float* probs = (const float*)d_in[0];
    const float* image = (const float*)d_in[1];
    float* out = (float*)d_out;
    crf_fused<<<NBLK, TPB>>>(probs, image, out);
}

// round 5
// speedup vs baseline: 1.1794x; 1.1794x over previous
#include <cuda_runtime.h>

// Dense CRF pairwise loss, B=1, C=2, H=W=96.
// K_ij = 2^(g_i.g_j - h_i - h_j), g = 5-dim scaled feature, h = |g|^2/2.
// Tile-symmetry: sum over a<=b tile pairs, off-diag doubled.
// Per-i weight hoisted: Sum_j k*(A_i+B_i*p_j) = A_i*Sum k + B_i*Sum k*p_j.

#define Hdim   96
#define Wdim   96
#define NPIX   9216
#define TPB    768
#define IPT    2
#define ITILE  1536          // TPB*IPT
#define NTILES 6             // 9216/1536
#define NTPAIR 21            // triangle incl diagonal
#define NCHUNK 7
#define NBLK   (NTPAIR*NCHUNK)  // 147 blocks = 1 wave on 148 SMs
#define JP_TILE (ITILE/2)    // 768 j-pairs per tile
#define JPMAX  110           // ceil(768/7)

__device__ float g_part[NBLK];
__device__ int   g_cnt = 0;

typedef unsigned long long u64;

__device__ __forceinline__ u64 splat2(float v) {
    u64 r; asm("mov.b64 %0,{%1,%1};" : "=l"(r) : "f"(v)); return r;
}
__device__ __forceinline__ u64 pk2(float a, float b) {
    u64 r; asm("mov.b64 %0,{%1,%2};" : "=l"(r) : "f"(a), "f"(b)); return r;
}
__device__ __forceinline__ void up2(u64 v, float& a, float& b) {
    asm("mov.b64 {%0,%1},%2;" : "=f"(a), "=f"(b) : "l"(v));
}
__device__ __forceinline__ u64 fma2(u64 a, u64 b, u64 c) {
    u64 d; asm("fma.rn.f32x2 %0,%1,%2,%3;" : "=l"(d) : "l"(a), "l"(b), "l"(c)); return d;
}
__device__ __forceinline__ u64 add2(u64 a, u64 b) {
    u64 d; asm("add.rn.f32x2 %0,%1,%2;" : "=l"(d) : "l"(a), "l"(b)); return d;
}
__device__ __forceinline__ float ex2f(float x) {
    float r; asm("ex2.approx.ftz.f32 %0,%1;" : "=f"(r) : "f"(x)); return r;
}

__device__ __forceinline__ void pix_feat(const float* __restrict__ probs,
                                         const float* __restrict__ image, int n,
                                         float& gy, float& gx, float& gr, float& gg,
                                         float& gb, float& nh, float& p) {
    const float SXY  = 0.080074306f;   // sqrt(log2e/225)
    const float SRGB = 9.6083684f;     // sqrt(64*log2e)
    gy = (float)(n / Wdim) * SXY;
    gx = (float)(n % Wdim) * SXY;
    gr = image[n] * SRGB;
    gg = image[NPIX + n] * SRGB;
    gb = image[2 * NPIX + n] * SRGB;
    nh = -0.5f * (gy*gy + gx*gx + gr*gr + gg*gg + gb*gb);
    p  = probs[n];
}

__global__ void __launch_bounds__(TPB) crf_fused(const float* __restrict__ probs,
                                                 const float* __restrict__ image,
                                                 float* __restrict__ out) {
    // j-features packed as f32x2 pairs: LDS.128 reg pairs feed fma.f32x2 directly
    __shared__ ulonglong2 sA[JPMAX];   // {gy01, gx01}
    __shared__ ulonglong2 sB[JPMAX];   // {gr01, gg01}
    __shared__ ulonglong2 sC[JPMAX];   // {gb01, nh01}
    __shared__ u64        sP[JPMAX];   // p01
    __shared__ float      ws[TPB / 32];
    __shared__ bool       isLast;

    const int tid = threadIdx.x;
    const int bid = blockIdx.x;
    const int pairIdx = bid / NCHUNK;
    const int chunk   = bid % NCHUNK;

    int a = 0, b = 0, idx = pairIdx;
    #pragma unroll
    for (int aa = 0; aa < NTILES; ++aa) {
        int cnt = NTILES - aa;
        if (idx < cnt) { a = aa; b = aa + idx; break; }
        idx -= cnt;
    }

    const int jp0 = b * JP_TILE + (chunk * JP_TILE) / NCHUNK;
    const int jp1 = b * JP_TILE + ((chunk + 1) * JP_TILE) / NCHUNK;
    const int nJp = jp1 - jp0;

    if (tid < nJp) {
        int j0 = 2 * (jp0 + tid);
        float gy0, gx0, gr0, gg0, gb0, nh0, p0;
        float gy1, gx1, gr1, gg1, gb1, nh1, p1;
        pix_feat(probs, image, j0,     gy0, gx0, gr0, gg0, gb0, nh0, p0);
        pix_feat(probs, image, j0 + 1, gy1, gx1, gr1, gg1, gb1, nh1, p1);
        sA[tid] = make_ulonglong2(pk2(gy0, gy1), pk2(gx0, gx1));
        sB[tid] = make_ulonglong2(pk2(gr0, gr1), pk2(gg0, gg1));
        sC[tid] = make_ulonglong2(pk2(gb0, gb1), pk2(nh0, nh1));
        sP[tid] = pk2(p0, p1);
    }

    const float wscale = (a == b) ? 1.0f : 2.0f;
    u64 gyi[IPT], gxi[IPT], gri[IPT], ggi[IPT], gbi[IPT], nhi[IPT];
    u64 accA[IPT], accB[IPT];          // Sum k ; Sum k*pj
    float Ai[IPT], Bi[IPT];
    #pragma unroll
    for (int m = 0; m < IPT; ++m) {
        int i = a * ITILE + tid + m * TPB;
        float gy, gx, gr, gg, gb, nh, p;
        pix_feat(probs, image, i, gy, gx, gr, gg, gb, nh, p);
        gyi[m] = splat2(gy); gxi[m] = splat2(gx);
        gri[m] = splat2(gr); ggi[m] = splat2(gg); gbi[m] = splat2(gb);
        nhi[m] = splat2(nh);
        Ai[m] = wscale * p;
        Bi[m] = wscale * (1.0f - 2.0f * p);
        accA[m] = 0ull; accB[m] = 0ull;
    }
    __syncthreads();

    #pragma unroll 2
    for (int jp = 0; jp < nJp; ++jp) {
        ulonglong2 A = sA[jp], B = sB[jp], C = sC[jp];
        u64 pj = sP[jp];
        #pragma unroll
        for (int m = 0; m < IPT; ++m) {
            u64 t = add2(nhi[m], C.y);
            t = fma2(gyi[m], A.x, t);
            t = fma2(gxi[m], A.y, t);
            t = fma2(gri[m], B.x, t);
            t = fma2(ggi[m], B.y, t);
            t = fma2(gbi[m], C.x, t);
            float t0, t1; up2(t, t0, t1);
            u64 k = pk2(ex2f(t0), ex2f(t1));
            accA[m] = add2(accA[m], k);
            accB[m] = fma2(k, pj, accB[m]);
        }
    }

    // apply per-i weights, block reduce (fixed order -> deterministic)
    float s = 0.0f;
    #pragma unroll
    for (int m = 0; m < IPT; ++m) {
        float a0, a1, b0, b1;
        up2(accA[m], a0, a1);
        up2(accB[m], b0, b1);
        s += Ai[m] * (a0 + a1) + Bi[m] * (b0 + b1);
    }
    #pragma unroll
    for (int off = 16; off > 0; off >>= 1)
        s += __shfl_down_sync(0xffffffffu, s, off);
    if ((tid & 31) == 0) ws[tid >> 5] = s;
    __syncthreads();
    if (tid == 0) {
        float t = 0.0f;
        #pragma unroll
        for (int k = 0; k < TPB / 32; ++k) t += ws[k];
        g_part[bid] = t;
        __threadfence();
        int old = atomicAdd(&g_cnt, 1);
        isLast = (old == NBLK - 1);
    }
    __syncthreads();
    if (isLast && tid < 32) {
        __threadfence();
        float acc2 = 0.0f;
        #pragma unroll
        for (int k = tid; k < NBLK; k += 32) acc2 += __ldcg(&g_part[k]);
        #pragma unroll
        for (int off = 16; off > 0; off >>= 1)
            acc2 += __shfl_down_sync(0xffffffffu, acc2, off);
        if (tid == 0) {
            out[0] = acc2 * (1.0f / (float)NPIX);
            g_cnt = 0;   // reset for next graph replay
        }
    }
}

extern "C" void kernel_launch(void* const* d_in, const int* in_sizes, int n_in,
                              void* d_out, int out_size) {
    const float* probs = (const float*)d_in[0];
    const float* image = (const float*)d_in[1];
    float* out = (float*)d_out;
    crf_fused<<<NBLK, TPB>>>(probs, image, out);
}